// round 3
// baseline (speedup 1.0000x reference)
#include <cuda_runtime.h>
#include <cuda_bf16.h>
#include <math.h>

// ---------------------------------------------------------------------------
// Problem shapes
//   B=128, T=46, V=8150, E=300, H=128, 4H=512
//   x: [B,T,V]  embed: [V,E]  W_lstm: [E+H, 4H]  lng/lnb: [5,H]
//   out: [B,2] float32
// ---------------------------------------------------------------------------

#define BATCH 128
#define TT    46
#define VV    8150
#define EE    300
#define HH    128
#define ZC    512          // 4H
#define MROWS (BATCH*TT)   // 5888

// ------------------------- scratch (device globals) ------------------------
__device__ float g_e[2L * MROWS * EE];     // embeddings, both branches
__device__ float g_zx[2L * MROWS * ZC];    // precomputed x-part of z
__device__ float g_h[2L * BATCH * TT * HH];// lstm outputs
__device__ float g_a[BATCH * 1024];        // concat(a1,a2)
__device__ float g_hidden[BATCH * 512];

// ---------------------------------------------------------------------------
// Generic fp32 SGEMM:  C = act(A[MxK] @ B[KxN] + bias)
// 128x128 tile, BK=8, 256 threads, 8x8 microtile.
// ---------------------------------------------------------------------------
#define BM 128
#define BN 128
#define BK 8

__global__ void __launch_bounds__(256, 2) sgemm_kernel(
    const float* __restrict__ A, const float* __restrict__ B,
    const float* __restrict__ bias, float* __restrict__ C,
    int M, int N, int K, int lda, int ldb, int ldc, int do_relu)
{
    __shared__ float As[BK][BM];
    __shared__ float Bs[BK][BN];

    const int tid  = threadIdx.x;
    const int row0 = blockIdx.y * BM;
    const int col0 = blockIdx.x * BN;
    const int tr   = tid >> 4;       // 0..15
    const int tc   = tid & 15;       // 0..15

    // global-load mapping
    const int a_m  = tid >> 1;             // 0..127
    const int a_k0 = (tid & 1) * 4;        // 0 or 4
    const int b_k  = (tid * 4) >> 7;       // 0..7
    const int b_n  = (tid * 4) & 127;

    float acc[8][8];
    #pragma unroll
    for (int i = 0; i < 8; i++)
        #pragma unroll
        for (int j = 0; j < 8; j++) acc[i][j] = 0.f;

    for (int k0 = 0; k0 < K; k0 += BK) {
        #pragma unroll
        for (int i = 0; i < 4; i++) {
            int k = k0 + a_k0 + i;
            int m = row0 + a_m;
            As[a_k0 + i][a_m] = (k < K && m < M) ? A[(size_t)m * lda + k] : 0.f;
        }
        #pragma unroll
        for (int i = 0; i < 4; i++) {
            int k = k0 + b_k;
            int n = col0 + b_n + i;
            Bs[b_k][b_n + i] = (k < K && n < N) ? B[(size_t)k * ldb + n] : 0.f;
        }
        __syncthreads();

        #pragma unroll
        for (int kk = 0; kk < BK; kk++) {
            float4 a0 = *(const float4*)&As[kk][tr * 8];
            float4 a1 = *(const float4*)&As[kk][tr * 8 + 4];
            float4 b0 = *(const float4*)&Bs[kk][tc * 8];
            float4 b1 = *(const float4*)&Bs[kk][tc * 8 + 4];
            float af[8] = {a0.x,a0.y,a0.z,a0.w,a1.x,a1.y,a1.z,a1.w};
            float bf[8] = {b0.x,b0.y,b0.z,b0.w,b1.x,b1.y,b1.z,b1.w};
            #pragma unroll
            for (int i = 0; i < 8; i++)
                #pragma unroll
                for (int j = 0; j < 8; j++)
                    acc[i][j] += af[i] * bf[j];
        }
        __syncthreads();
    }

    #pragma unroll
    for (int i = 0; i < 8; i++) {
        int m = row0 + tr * 8 + i;
        if (m >= M) continue;
        #pragma unroll
        for (int j = 0; j < 8; j++) {
            int n = col0 + tc * 8 + j;
            if (n >= N) continue;
            float v = acc[i][j];
            if (bias) v += bias[n];
            if (do_relu) v = fmaxf(v, 0.f);
            C[(size_t)m * ldc + n] = v;
        }
    }
}

// ---------------------------------------------------------------------------
// LSTM (both branches). One block = 4 batch elements of one branch.
// grid = 64 blocks (32 per branch), 512 threads (one per z column).
// W_h rows [0,96) in smem fp32; rows [96,128) streamed from L2.
// ---------------------------------------------------------------------------
#define LG 4            // batch elems per block
#define WSR 96          // W rows held in smem (96*512*4 = 196.6 KB)

__device__ __forceinline__ float sigf(float x) { return 1.f / (1.f + expf(-x)); }

__global__ void __launch_bounds__(512, 1) lstm_kernel(
    const float* __restrict__ zx,     // [2][MROWS][512]
    const float* __restrict__ W1, const float* __restrict__ W2,  // [428][512]
    const float* __restrict__ lng1, const float* __restrict__ lnb1,
    const float* __restrict__ lng2, const float* __restrict__ lnb2,
    float* __restrict__ hout)         // [2][B][T][H]
{
    extern __shared__ float sm[];
    float* Ws   = sm;                          // [WSR][512]
    float* hs   = Ws + WSR * 512;              // [128][4]  (k-major, float4 rows)
    float* cs   = hs + 128 * 4;                // [4][128]
    float* ex   = cs + 4 * 128;                // [4 q][4 g][128]
    float* redb = ex + 4 * 4 * 128;            // [16 warps][4 g][2]
    float* red2 = redb + 16 * 4 * 2;           // [4 warps][4 g][2]

    const int bx = blockIdx.x;
    const int br = bx >> 5;
    const int b0 = (bx & 31) * LG;
    const float* Wrec = (br ? W2 : W1) + 300 * 512;   // recurrent rows
    const float* lng  = br ? lng2 : lng1;
    const float* lnb  = br ? lnb2 : lnb1;
    const float* zxp  = zx + (size_t)br * MROWS * ZC;

    const int tid  = threadIdx.x;
    const int col  = tid;            // z column 0..511
    const int gate = col >> 7;       // 0:i 1:j 2:f 3:o
    const int hc   = col & 127;
    const int warp = tid >> 5;
    const int lane = tid & 31;

    // load W slab
    for (int idx = tid; idx < WSR * 512; idx += 512) Ws[idx] = Wrec[idx];
    // zero h, c
    for (int idx = tid; idx < 128 * 4; idx += 512) hs[idx] = 0.f;
    if (tid < 4 * 128) cs[tid] = 0.f;

    const float gamma = lng[gate * HH + hc];
    const float beta  = lnb[gate * HH + hc];
    float g4 = 0.f, b4 = 0.f;
    if (tid < 128) { g4 = lng[4 * HH + hc]; b4 = lnb[4 * HH + hc]; }

    __syncthreads();

    for (int t = 0; t < TT; t++) {
        // ---- z = zx + h @ W_h -------------------------------------------
        float z[LG];
        #pragma unroll
        for (int g = 0; g < LG; g++)
            z[g] = zxp[((size_t)(b0 + g) * TT + t) * ZC + col];

        #pragma unroll 8
        for (int k = 0; k < WSR; k++) {
            float w = Ws[k * 512 + col];
            float4 h4 = *(const float4*)&hs[k * 4];
            z[0] += h4.x * w; z[1] += h4.y * w; z[2] += h4.z * w; z[3] += h4.w * w;
        }
        #pragma unroll
        for (int k = WSR; k < 128; k++) {
            float w = __ldg(&Wrec[k * 512 + col]);
            float4 h4 = *(const float4*)&hs[k * 4];
            z[0] += h4.x * w; z[1] += h4.y * w; z[2] += h4.z * w; z[3] += h4.w * w;
        }

        // ---- per-gate LayerNorm (reduce over 128 cols of this gate) -----
        float s1[LG], s2[LG];
        #pragma unroll
        for (int g = 0; g < LG; g++) { s1[g] = z[g]; s2[g] = z[g] * z[g]; }
        #pragma unroll
        for (int o = 16; o > 0; o >>= 1) {
            #pragma unroll
            for (int g = 0; g < LG; g++) {
                s1[g] += __shfl_down_sync(0xffffffffu, s1[g], o);
                s2[g] += __shfl_down_sync(0xffffffffu, s2[g], o);
            }
        }
        if (lane == 0) {
            #pragma unroll
            for (int g = 0; g < LG; g++) {
                redb[(warp * 4 + g) * 2 + 0] = s1[g];
                redb[(warp * 4 + g) * 2 + 1] = s2[g];
            }
        }
        __syncthreads();
        const int wb = gate * 4;
        #pragma unroll
        for (int g = 0; g < LG; g++) {
            float m1 = 0.f, m2 = 0.f;
            #pragma unroll
            for (int w = 0; w < 4; w++) {
                m1 += redb[((wb + w) * 4 + g) * 2 + 0];
                m2 += redb[((wb + w) * 4 + g) * 2 + 1];
            }
            float mean = m1 * (1.f / 128.f);
            float var  = m2 * (1.f / 128.f) - mean * mean;
            float inv  = 1.f / sqrtf(var + 1e-12f);
            float zn   = (z[g] - mean) * inv * gamma + beta;
            float q;
            if      (gate == 0) q = sigf(zn);            // sigmoid(i)
            else if (gate == 1) q = fmaxf(zn, 0.f);      // relu(j)
            else if (gate == 2) q = sigf(zn + 1.f);      // sigmoid(f+1)
            else                q = sigf(zn);            // sigmoid(o)
            ex[(gate * LG + g) * 128 + hc] = q;
        }
        __syncthreads();

        // ---- cell/hidden update (threads 0..127, hc = tid) --------------
        float nc[LG];
        if (tid < 128) {
            float t1[LG], t2[LG];
            #pragma unroll
            for (int g = 0; g < LG; g++) {
                float si = ex[(0 * LG + g) * 128 + tid];
                float rj = ex[(1 * LG + g) * 128 + tid];
                float sf = ex[(2 * LG + g) * 128 + tid];
                float c  = cs[g * 128 + tid];
                nc[g] = c * sf + si * rj;
                cs[g * 128 + tid] = nc[g];
                t1[g] = nc[g]; t2[g] = nc[g] * nc[g];
            }
            #pragma unroll
            for (int o = 16; o > 0; o >>= 1) {
                #pragma unroll
                for (int g = 0; g < LG; g++) {
                    t1[g] += __shfl_down_sync(0xffffffffu, t1[g], o);
                    t2[g] += __shfl_down_sync(0xffffffffu, t2[g], o);
                }
            }
            if (lane == 0) {
                #pragma unroll
                for (int g = 0; g < LG; g++) {
                    red2[(warp * 4 + g) * 2 + 0] = t1[g];
                    red2[(warp * 4 + g) * 2 + 1] = t2[g];
                }
            }
        }
        __syncthreads();
        if (tid < 128) {
            #pragma unroll
            for (int g = 0; g < LG; g++) {
                float m1 = 0.f, m2 = 0.f;
                #pragma unroll
                for (int w = 0; w < 4; w++) {
                    m1 += red2[(w * 4 + g) * 2 + 0];
                    m2 += red2[(w * 4 + g) * 2 + 1];
                }
                float mean = m1 * (1.f / 128.f);
                float var  = m2 * (1.f / 128.f) - mean * mean;
                float inv  = 1.f / sqrtf(var + 1e-12f);
                float lc   = (nc[g] - mean) * inv * g4 + b4;
                float nh   = fmaxf(lc, 0.f) * ex[(3 * LG + g) * 128 + tid];
                hs[tid * 4 + g] = nh;
                hout[(((size_t)br * BATCH + b0 + g) * TT + t) * HH + tid] = nh;
            }
        }
        __syncthreads();
    }
}

// ---------------------------------------------------------------------------
// Attention: softmax over T of <o_t, v>, context, dense(512)+relu.
// grid (128 batch, 2 branch), 128 threads.
// ---------------------------------------------------------------------------
__global__ void __launch_bounds__(128) attn_kernel(
    const float* __restrict__ hbuf,  // [2][B][T][H]
    const float* __restrict__ v1, const float* __restrict__ Wo1, const float* __restrict__ bo1,
    const float* __restrict__ v2, const float* __restrict__ Wo2, const float* __restrict__ bo2,
    float* __restrict__ aout)        // [B][1024]
{
    __shared__ float os[TT][HH];
    __shared__ float sc[64];
    __shared__ float ctxs[HH];

    const int b  = blockIdx.x;
    const int br = blockIdx.y;
    const float* v  = br ? v2  : v1;
    const float* Wo = br ? Wo2 : Wo1;
    const float* bo = br ? bo2 : bo1;

    const int tid  = threadIdx.x;
    const int warp = tid >> 5;
    const int lane = tid & 31;

    const float* hb = hbuf + ((size_t)br * BATCH + b) * TT * HH;
    for (int idx = tid; idx < TT * HH; idx += 128)
        ((float*)os)[idx] = hb[idx];

    float vr[4];
    #pragma unroll
    for (int j = 0; j < 4; j++) vr[j] = v[lane + 32 * j];
    __syncthreads();

    // scores
    for (int t = warp; t < TT; t += 4) {
        float p = 0.f;
        #pragma unroll
        for (int j = 0; j < 4; j++) p += os[t][lane + 32 * j] * vr[j];
        #pragma unroll
        for (int o = 16; o > 0; o >>= 1) p += __shfl_down_sync(0xffffffffu, p, o);
        if (lane == 0) sc[t] = p;
    }
    __syncthreads();

    // softmax over 46 (warp 0)
    if (warp == 0) {
        float x0 = (lane      < TT) ? sc[lane]      : -1e30f;
        float x1 = (lane + 32 < TT) ? sc[lane + 32] : -1e30f;
        float m = fmaxf(x0, x1);
        #pragma unroll
        for (int o = 16; o > 0; o >>= 1) m = fmaxf(m, __shfl_xor_sync(0xffffffffu, m, o));
        float e0 = (lane      < TT) ? expf(x0 - m) : 0.f;
        float e1 = (lane + 32 < TT) ? expf(x1 - m) : 0.f;
        float s = e0 + e1;
        #pragma unroll
        for (int o = 16; o > 0; o >>= 1) s += __shfl_xor_sync(0xffffffffu, s, o);
        float invs = 1.f / s;
        if (lane < TT)      sc[lane]      = e0 * invs;
        if (lane + 32 < TT) sc[lane + 32] = e1 * invs;
    }
    __syncthreads();

    // context
    float c = 0.f;
    for (int t = 0; t < TT; t++) c += sc[t] * os[t][tid];
    ctxs[tid] = c;
    __syncthreads();

    // dense 512 + relu
    #pragma unroll
    for (int j = 0; j < 4; j++) {
        int n = tid + 128 * j;
        float acc = bo[n];
        #pragma unroll 4
        for (int h = 0; h < HH; h++) acc += ctxs[h] * __ldg(&Wo[h * 512 + n]);
        aout[(size_t)b * 1024 + br * 512 + n] = fmaxf(acc, 0.f);
    }
}

// ---------------------------------------------------------------------------
// Final logits: out[b][j] = hidden[b] . W_out[:,j] + b_out[j]
// ---------------------------------------------------------------------------
__global__ void __launch_bounds__(256) head_kernel(
    const float* __restrict__ hidden, const float* __restrict__ Wout,
    const float* __restrict__ bout, float* __restrict__ out)
{
    int tid = threadIdx.x;
    int b = tid >> 1, j = tid & 1;
    float acc = bout[j];
    #pragma unroll 4
    for (int k = 0; k < 512; k++) acc += hidden[b * 512 + k] * Wout[k * 2 + j];
    out[b * 2 + j] = acc;
}

// ---------------------------------------------------------------------------
extern "C" void kernel_launch(void* const* d_in, const int* in_sizes, int n_in,
                              void* d_out, int out_size)
{
    const float* x1    = (const float*)d_in[0];
    const float* x2    = (const float*)d_in[1];
    const float* emb1  = (const float*)d_in[2];
    const float* emb2  = (const float*)d_in[3];
    const float* Wl1   = (const float*)d_in[4];
    const float* Wl2   = (const float*)d_in[5];
    const float* lng1  = (const float*)d_in[6];
    const float* lnb1  = (const float*)d_in[7];
    const float* lng2  = (const float*)d_in[8];
    const float* lnb2  = (const float*)d_in[9];
    const float* av1   = (const float*)d_in[10];
    const float* aWo1  = (const float*)d_in[11];
    const float* abo1  = (const float*)d_in[12];
    const float* av2   = (const float*)d_in[13];
    const float* aWo2  = (const float*)d_in[14];
    const float* abo2  = (const float*)d_in[15];
    const float* Wh    = (const float*)d_in[16];
    const float* bh    = (const float*)d_in[17];
    const float* Wout  = (const float*)d_in[18];
    const float* bout  = (const float*)d_in[19];
    float* out = (float*)d_out;

    float *pe, *pzx, *ph, *pa, *phid;
    cudaGetSymbolAddress((void**)&pe,   g_e);
    cudaGetSymbolAddress((void**)&pzx,  g_zx);
    cudaGetSymbolAddress((void**)&ph,   g_h);
    cudaGetSymbolAddress((void**)&pa,   g_a);
    cudaGetSymbolAddress((void**)&phid, g_hidden);

    const int lstm_smem = (WSR * 512 + 128 * 4 + 4 * 128 + 4 * 4 * 128 + 16 * 4 * 2 + 4 * 4 * 2) * 4;
    cudaFuncSetAttribute(lstm_kernel, cudaFuncAttributeMaxDynamicSharedMemorySize, lstm_smem);

    // 1) embeddings: e = x @ embed   [5888 x 300], K=8150
    sgemm_kernel<<<dim3(3, 46), 256>>>(x1, emb1, nullptr, pe,
                                       MROWS, EE, VV, VV, EE, EE, 0);
    sgemm_kernel<<<dim3(3, 46), 256>>>(x2, emb2, nullptr, pe + (size_t)MROWS * EE,
                                       MROWS, EE, VV, VV, EE, EE, 0);

    // 2) zx = e @ W_lstm[0:300]   [5888 x 512], K=300
    sgemm_kernel<<<dim3(4, 46), 256>>>(pe, Wl1, nullptr, pzx,
                                       MROWS, ZC, EE, EE, ZC, ZC, 0);
    sgemm_kernel<<<dim3(4, 46), 256>>>(pe + (size_t)MROWS * EE, Wl2, nullptr,
                                       pzx + (size_t)MROWS * ZC,
                                       MROWS, ZC, EE, EE, ZC, ZC, 0);

    // 3) recurrent LSTM, both branches
    lstm_kernel<<<64, 512, lstm_smem>>>(pzx, Wl1, Wl2, lng1, lnb1, lng2, lnb2, ph);

    // 4) attention + dense(512,relu), both branches
    attn_kernel<<<dim3(BATCH, 2), 128>>>(ph, av1, aWo1, abo1, av2, aWo2, abo2, pa);

    // 5) hidden = relu(concat @ W_h + b_h)   [128 x 512], K=1024
    sgemm_kernel<<<dim3(4, 1), 256>>>(pa, Wh, bh, phid,
                                      BATCH, 512, 1024, 1024, 512, 512, 1);

    // 6) logits
    head_kernel<<<1, 256>>>(phid, Wout, bout, out);
}

// round 4
// speedup vs baseline: 1.8352x; 1.8352x over previous
#include <cuda_runtime.h>
#include <cuda_bf16.h>
#include <math.h>
#include <stdint.h>

// ---------------------------------------------------------------------------
// Problem shapes
//   B=128, T=46, V=8150, E=300, H=128, 4H=512
// ---------------------------------------------------------------------------
#define BATCH 128
#define TT    46
#define VV    8150
#define EE    300
#define HH    128
#define ZC    512
#define MROWS (BATCH*TT)   // 5888

#define KSEG  8160         // V padded to multiple of 32
#define NPAD  320          // E padded to multiple of 64

// ------------------------- scratch (device globals) ------------------------
__device__ __nv_bfloat16 g_xhi[2L * MROWS * KSEG];
__device__ __nv_bfloat16 g_xlo[2L * MROWS * KSEG];
__device__ __nv_bfloat16 g_ehiT[2L * NPAD * KSEG];   // [br][n][k]
__device__ __nv_bfloat16 g_eloT[2L * NPAD * KSEG];
__device__ float g_e[2L * MROWS * EE];     // embeddings fp32
__device__ float g_zx[2L * MROWS * ZC];    // precomputed x-part of z
__device__ float g_h[2L * BATCH * TT * HH];
__device__ float g_a[BATCH * 1024];
__device__ float g_hidden[BATCH * 512];

// ---------------------------------------------------------------------------
// Conversion: x -> bf16 hi/lo, padded [2][MROWS][KSEG]
// ---------------------------------------------------------------------------
__global__ void __launch_bounds__(256) convx_kernel(
    const float* __restrict__ x1, const float* __restrict__ x2,
    __nv_bfloat16* __restrict__ xhi, __nv_bfloat16* __restrict__ xlo)
{
    size_t t = (size_t)blockIdx.x * blockDim.x + threadIdx.x;
    size_t nquad = (2L * MROWS * KSEG) / 4;
    if (t >= nquad) return;
    size_t base = t * 4;
    size_t row = base / KSEG;            // 0 .. 2*MROWS-1
    int k = (int)(base % KSEG);          // multiple of 4
    const float* x = (row < MROWS) ? x1 : x2;
    size_t m = (row < MROWS) ? row : row - MROWS;
    #pragma unroll
    for (int i = 0; i < 4; i++) {
        int kk = k + i;
        float v = (kk < VV) ? x[m * VV + kk] : 0.f;
        __nv_bfloat16 h = __float2bfloat16(v);
        __nv_bfloat16 l = __float2bfloat16(v - __bfloat162float(h));
        xhi[base + i] = h;
        xlo[base + i] = l;
    }
}

// embed [V,E] -> transposed padded bf16 hi/lo [2][NPAD][KSEG]
__global__ void __launch_bounds__(256) conve_kernel(
    const float* __restrict__ e1, const float* __restrict__ e2,
    __nv_bfloat16* __restrict__ ehiT, __nv_bfloat16* __restrict__ eloT)
{
    size_t idx = (size_t)blockIdx.x * blockDim.x + threadIdx.x;
    size_t tot = 2L * NPAD * KSEG;
    if (idx >= tot) return;
    size_t br  = idx / ((size_t)NPAD * KSEG);
    size_t rem = idx % ((size_t)NPAD * KSEG);
    int n = (int)(rem / KSEG);
    int k = (int)(rem % KSEG);
    const float* e = br ? e2 : e1;
    float v = (n < EE && k < VV) ? e[(size_t)k * EE + n] : 0.f;
    __nv_bfloat16 h = __float2bfloat16(v);
    __nv_bfloat16 l = __float2bfloat16(v - __bfloat162float(h));
    ehiT[idx] = h;
    eloT[idx] = l;
}

// ---------------------------------------------------------------------------
// bf16 split-GEMM for embeddings:  e = x @ embed  via 3-segment K extension
//   seg0: xhi*ehi  seg1: xhi*elo  seg2: xlo*ehi
// Tile 128x64x32, 256 threads (8 warps, 4x2), warp tile 32x32, mma m16n8k16.
// ---------------------------------------------------------------------------
#define GBM 128
#define GBN 64
#define GBK 32
#define SPAD 40                      // smem row stride (bf16 elems)
#define SEGIT (KSEG / GBK)           // 255
#define NITER (3 * SEGIT)            // 765

__device__ __forceinline__ void cpa16(void* sdst, const void* gsrc) {
    uint32_t s = (uint32_t)__cvta_generic_to_shared(sdst);
    asm volatile("cp.async.ca.shared.global [%0], [%1], 16;\n" :: "r"(s), "l"(gsrc));
}
__device__ __forceinline__ uint32_t ld32s(const __nv_bfloat16* p) {
    return *(const uint32_t*)p;
}
__device__ __forceinline__ void mma16816(float* c, const uint32_t* a, const uint32_t* b) {
    asm volatile(
        "mma.sync.aligned.m16n8k16.row.col.f32.bf16.bf16.f32 "
        "{%0,%1,%2,%3}, {%4,%5,%6,%7}, {%8,%9}, {%0,%1,%2,%3};\n"
        : "+f"(c[0]), "+f"(c[1]), "+f"(c[2]), "+f"(c[3])
        : "r"(a[0]), "r"(a[1]), "r"(a[2]), "r"(a[3]), "r"(b[0]), "r"(b[1]));
}

__global__ void __launch_bounds__(256, 2) emb_mma_kernel(
    const __nv_bfloat16* __restrict__ xhi_, const __nv_bfloat16* __restrict__ xlo_,
    const __nv_bfloat16* __restrict__ ehiT_, const __nv_bfloat16* __restrict__ eloT_,
    float* __restrict__ eout_)
{
    __shared__ __nv_bfloat16 As[2][GBM * SPAD];
    __shared__ __nv_bfloat16 Bs[2][GBN * SPAD];

    const int z = blockIdx.z;
    const __nv_bfloat16* xhi  = xhi_  + (size_t)z * MROWS * KSEG;
    const __nv_bfloat16* xlo  = xlo_  + (size_t)z * MROWS * KSEG;
    const __nv_bfloat16* ehiT = ehiT_ + (size_t)z * NPAD * KSEG;
    const __nv_bfloat16* eloT = eloT_ + (size_t)z * NPAD * KSEG;
    float* eout = eout_ + (size_t)z * MROWS * EE;

    const int tid  = threadIdx.x;
    const int lane = tid & 31;
    const int warp = tid >> 5;
    const int wm   = warp >> 1;      // 0..3
    const int wn   = warp & 1;       // 0..1
    const int mbase = blockIdx.y * GBM;
    const int nbase = blockIdx.x * GBN;

    float acc[2][4][4];
    #pragma unroll
    for (int mt = 0; mt < 2; mt++)
        #pragma unroll
        for (int nt = 0; nt < 4; nt++)
            #pragma unroll
            for (int i = 0; i < 4; i++) acc[mt][nt][i] = 0.f;

    // tile loader
    auto load_tiles = [&](int buf, int it) {
        const __nv_bfloat16 *Aseg, *Bseg;
        int kof;
        if (it < SEGIT)            { Aseg = xhi; Bseg = ehiT; kof = it * GBK; }
        else if (it < 2 * SEGIT)   { Aseg = xhi; Bseg = eloT; kof = (it - SEGIT) * GBK; }
        else                       { Aseg = xlo; Bseg = ehiT; kof = (it - 2 * SEGIT) * GBK; }
        #pragma unroll
        for (int i = 0; i < 2; i++) {
            int c = tid + 256 * i;
            int r = c >> 2, co = (c & 3) * 8;
            cpa16(&As[buf][r * SPAD + co], Aseg + (size_t)(mbase + r) * KSEG + kof + co);
        }
        {
            int r = tid >> 2, co = (tid & 3) * 8;
            cpa16(&Bs[buf][r * SPAD + co], Bseg + (size_t)(nbase + r) * KSEG + kof + co);
        }
        asm volatile("cp.async.commit_group;\n" ::: "memory");
    };

    load_tiles(0, 0);

    for (int it = 0; it < NITER; it++) {
        const int cur = it & 1;
        __syncthreads();                 // prev-buffer consumers done
        if (it + 1 < NITER) {
            load_tiles(cur ^ 1, it + 1);
            asm volatile("cp.async.wait_group 1;\n" ::: "memory");
        } else {
            asm volatile("cp.async.wait_group 0;\n" ::: "memory");
        }
        __syncthreads();                 // current buffer visible

        const __nv_bfloat16* Ab = As[cur];
        const __nv_bfloat16* Bb = Bs[cur];
        #pragma unroll
        for (int s = 0; s < 2; s++) {
            const int c = s * 16 + (lane & 3) * 2;
            uint32_t a[2][4], b[4][2];
            #pragma unroll
            for (int mt = 0; mt < 2; mt++) {
                int r = wm * 32 + mt * 16 + (lane >> 2);
                a[mt][0] = ld32s(&Ab[r * SPAD + c]);
                a[mt][1] = ld32s(&Ab[(r + 8) * SPAD + c]);
                a[mt][2] = ld32s(&Ab[r * SPAD + c + 8]);
                a[mt][3] = ld32s(&Ab[(r + 8) * SPAD + c + 8]);
            }
            #pragma unroll
            for (int nt = 0; nt < 4; nt++) {
                int nr = wn * 32 + nt * 8 + (lane >> 2);
                b[nt][0] = ld32s(&Bb[nr * SPAD + c]);
                b[nt][1] = ld32s(&Bb[nr * SPAD + c + 8]);
            }
            #pragma unroll
            for (int mt = 0; mt < 2; mt++)
                #pragma unroll
                for (int nt = 0; nt < 4; nt++)
                    mma16816(acc[mt][nt], a[mt], b[nt]);
        }
    }

    // epilogue (N bounds-checked against 300)
    #pragma unroll
    for (int mt = 0; mt < 2; mt++) {
        int r0 = mbase + wm * 32 + mt * 16 + (lane >> 2);
        #pragma unroll
        for (int nt = 0; nt < 4; nt++) {
            int c0 = nbase + wn * 32 + nt * 8 + (lane & 3) * 2;
            if (c0 < EE) {
                eout[(size_t)r0 * EE + c0]       = acc[mt][nt][0];
                eout[(size_t)(r0 + 8) * EE + c0] = acc[mt][nt][2];
            }
            if (c0 + 1 < EE) {
                eout[(size_t)r0 * EE + c0 + 1]       = acc[mt][nt][1];
                eout[(size_t)(r0 + 8) * EE + c0 + 1] = acc[mt][nt][3];
            }
        }
    }
}

// ---------------------------------------------------------------------------
// Generic fp32 SGEMM (zx + hidden layers): 128x128 tile, BK=8
// ---------------------------------------------------------------------------
#define BM 128
#define BN 128
#define BK 8

__global__ void __launch_bounds__(256, 2) sgemm_kernel(
    const float* __restrict__ A, const float* __restrict__ B,
    const float* __restrict__ bias, float* __restrict__ C,
    int M, int N, int K, int lda, int ldb, int ldc, int do_relu)
{
    __shared__ float As[BK][BM];
    __shared__ float Bs[BK][BN];

    const int tid  = threadIdx.x;
    const int row0 = blockIdx.y * BM;
    const int col0 = blockIdx.x * BN;
    const int tr   = tid >> 4;
    const int tc   = tid & 15;
    const int a_m  = tid >> 1;
    const int a_k0 = (tid & 1) * 4;
    const int b_k  = (tid * 4) >> 7;
    const int b_n  = (tid * 4) & 127;

    float acc[8][8];
    #pragma unroll
    for (int i = 0; i < 8; i++)
        #pragma unroll
        for (int j = 0; j < 8; j++) acc[i][j] = 0.f;

    for (int k0 = 0; k0 < K; k0 += BK) {
        #pragma unroll
        for (int i = 0; i < 4; i++) {
            int k = k0 + a_k0 + i;
            int m = row0 + a_m;
            As[a_k0 + i][a_m] = (k < K && m < M) ? A[(size_t)m * lda + k] : 0.f;
        }
        #pragma unroll
        for (int i = 0; i < 4; i++) {
            int k = k0 + b_k;
            int n = col0 + b_n + i;
            Bs[b_k][b_n + i] = (k < K && n < N) ? B[(size_t)k * ldb + n] : 0.f;
        }
        __syncthreads();
        #pragma unroll
        for (int kk = 0; kk < BK; kk++) {
            float4 a0 = *(const float4*)&As[kk][tr * 8];
            float4 a1 = *(const float4*)&As[kk][tr * 8 + 4];
            float4 b0 = *(const float4*)&Bs[kk][tc * 8];
            float4 b1 = *(const float4*)&Bs[kk][tc * 8 + 4];
            float af[8] = {a0.x,a0.y,a0.z,a0.w,a1.x,a1.y,a1.z,a1.w};
            float bf[8] = {b0.x,b0.y,b0.z,b0.w,b1.x,b1.y,b1.z,b1.w};
            #pragma unroll
            for (int i = 0; i < 8; i++)
                #pragma unroll
                for (int j = 0; j < 8; j++)
                    acc[i][j] += af[i] * bf[j];
        }
        __syncthreads();
    }

    #pragma unroll
    for (int i = 0; i < 8; i++) {
        int m = row0 + tr * 8 + i;
        if (m >= M) continue;
        #pragma unroll
        for (int j = 0; j < 8; j++) {
            int n = col0 + tc * 8 + j;
            if (n >= N) continue;
            float v = acc[i][j];
            if (bias) v += bias[n];
            if (do_relu) v = fmaxf(v, 0.f);
            C[(size_t)m * ldc + n] = v;
        }
    }
}

// ---------------------------------------------------------------------------
// LSTM (both branches). One block = 4 batch elems. 512 threads.
// ---------------------------------------------------------------------------
#define LG 4
#define WSR 96

__device__ __forceinline__ float sigf(float x) { return 1.f / (1.f + expf(-x)); }

__global__ void __launch_bounds__(512, 1) lstm_kernel(
    const float* __restrict__ zx,
    const float* __restrict__ W1, const float* __restrict__ W2,
    const float* __restrict__ lng1, const float* __restrict__ lnb1,
    const float* __restrict__ lng2, const float* __restrict__ lnb2,
    float* __restrict__ hout)
{
    extern __shared__ float sm[];
    float* Ws   = sm;
    float* hs   = Ws + WSR * 512;
    float* cs   = hs + 128 * 4;
    float* ex   = cs + 4 * 128;
    float* redb = ex + 4 * 4 * 128;
    float* red2 = redb + 16 * 4 * 2;

    const int bx = blockIdx.x;
    const int br = bx >> 5;
    const int b0 = (bx & 31) * LG;
    const float* Wrec = (br ? W2 : W1) + 300 * 512;
    const float* lng  = br ? lng2 : lng1;
    const float* lnb  = br ? lnb2 : lnb1;
    const float* zxp  = zx + (size_t)br * MROWS * ZC;

    const int tid  = threadIdx.x;
    const int col  = tid;
    const int gate = col >> 7;
    const int hc   = col & 127;
    const int warp = tid >> 5;
    const int lane = tid & 31;

    for (int idx = tid; idx < WSR * 512; idx += 512) Ws[idx] = Wrec[idx];
    for (int idx = tid; idx < 128 * 4; idx += 512) hs[idx] = 0.f;
    if (tid < 4 * 128) cs[tid] = 0.f;

    const float gamma = lng[gate * HH + hc];
    const float beta  = lnb[gate * HH + hc];
    float g4 = 0.f, b4 = 0.f;
    if (tid < 128) { g4 = lng[4 * HH + hc]; b4 = lnb[4 * HH + hc]; }

    __syncthreads();

    for (int t = 0; t < TT; t++) {
        float z[LG];
        #pragma unroll
        for (int g = 0; g < LG; g++)
            z[g] = zxp[((size_t)(b0 + g) * TT + t) * ZC + col];

        #pragma unroll 8
        for (int k = 0; k < WSR; k++) {
            float w = Ws[k * 512 + col];
            float4 h4 = *(const float4*)&hs[k * 4];
            z[0] += h4.x * w; z[1] += h4.y * w; z[2] += h4.z * w; z[3] += h4.w * w;
        }
        #pragma unroll
        for (int k = WSR; k < 128; k++) {
            float w = __ldg(&Wrec[k * 512 + col]);
            float4 h4 = *(const float4*)&hs[k * 4];
            z[0] += h4.x * w; z[1] += h4.y * w; z[2] += h4.z * w; z[3] += h4.w * w;
        }

        float s1[LG], s2[LG];
        #pragma unroll
        for (int g = 0; g < LG; g++) { s1[g] = z[g]; s2[g] = z[g] * z[g]; }
        #pragma unroll
        for (int o = 16; o > 0; o >>= 1) {
            #pragma unroll
            for (int g = 0; g < LG; g++) {
                s1[g] += __shfl_down_sync(0xffffffffu, s1[g], o);
                s2[g] += __shfl_down_sync(0xffffffffu, s2[g], o);
            }
        }
        if (lane == 0) {
            #pragma unroll
            for (int g = 0; g < LG; g++) {
                redb[(warp * 4 + g) * 2 + 0] = s1[g];
                redb[(warp * 4 + g) * 2 + 1] = s2[g];
            }
        }
        __syncthreads();
        const int wb = gate * 4;
        #pragma unroll
        for (int g = 0; g < LG; g++) {
            float m1 = 0.f, m2 = 0.f;
            #pragma unroll
            for (int w = 0; w < 4; w++) {
                m1 += redb[((wb + w) * 4 + g) * 2 + 0];
                m2 += redb[((wb + w) * 4 + g) * 2 + 1];
            }
            float mean = m1 * (1.f / 128.f);
            float var  = m2 * (1.f / 128.f) - mean * mean;
            float inv  = 1.f / sqrtf(var + 1e-12f);
            float zn   = (z[g] - mean) * inv * gamma + beta;
            float q;
            if      (gate == 0) q = sigf(zn);
            else if (gate == 1) q = fmaxf(zn, 0.f);
            else if (gate == 2) q = sigf(zn + 1.f);
            else                q = sigf(zn);
            ex[(gate * LG + g) * 128 + hc] = q;
        }
        __syncthreads();

        float nc[LG];
        if (tid < 128) {
            float t1[LG], t2[LG];
            #pragma unroll
            for (int g = 0; g < LG; g++) {
                float si = ex[(0 * LG + g) * 128 + tid];
                float rj = ex[(1 * LG + g) * 128 + tid];
                float sf = ex[(2 * LG + g) * 128 + tid];
                float c  = cs[g * 128 + tid];
                nc[g] = c * sf + si * rj;
                cs[g * 128 + tid] = nc[g];
                t1[g] = nc[g]; t2[g] = nc[g] * nc[g];
            }
            #pragma unroll
            for (int o = 16; o > 0; o >>= 1) {
                #pragma unroll
                for (int g = 0; g < LG; g++) {
                    t1[g] += __shfl_down_sync(0xffffffffu, t1[g], o);
                    t2[g] += __shfl_down_sync(0xffffffffu, t2[g], o);
                }
            }
            if (lane == 0) {
                #pragma unroll
                for (int g = 0; g < LG; g++) {
                    red2[(warp * 4 + g) * 2 + 0] = t1[g];
                    red2[(warp * 4 + g) * 2 + 1] = t2[g];
                }
            }
        }
        __syncthreads();
        if (tid < 128) {
            #pragma unroll
            for (int g = 0; g < LG; g++) {
                float m1 = 0.f, m2 = 0.f;
                #pragma unroll
                for (int w = 0; w < 4; w++) {
                    m1 += red2[(w * 4 + g) * 2 + 0];
                    m2 += red2[(w * 4 + g) * 2 + 1];
                }
                float mean = m1 * (1.f / 128.f);
                float var  = m2 * (1.f / 128.f) - mean * mean;
                float inv  = 1.f / sqrtf(var + 1e-12f);
                float lc   = (nc[g] - mean) * inv * g4 + b4;
                float nh   = fmaxf(lc, 0.f) * ex[(3 * LG + g) * 128 + tid];
                hs[tid * 4 + g] = nh;
                hout[(((size_t)br * BATCH + b0 + g) * TT + t) * HH + tid] = nh;
            }
        }
        __syncthreads();
    }
}

// ---------------------------------------------------------------------------
// Attention + dense(512, relu)
// ---------------------------------------------------------------------------
__global__ void __launch_bounds__(128) attn_kernel(
    const float* __restrict__ hbuf,
    const float* __restrict__ v1, const float* __restrict__ Wo1, const float* __restrict__ bo1,
    const float* __restrict__ v2, const float* __restrict__ Wo2, const float* __restrict__ bo2,
    float* __restrict__ aout)
{
    __shared__ float os[TT][HH];
    __shared__ float sc[64];
    __shared__ float ctxs[HH];

    const int b  = blockIdx.x;
    const int br = blockIdx.y;
    const float* v  = br ? v2  : v1;
    const float* Wo = br ? Wo2 : Wo1;
    const float* bo = br ? bo2 : bo1;

    const int tid  = threadIdx.x;
    const int warp = tid >> 5;
    const int lane = tid & 31;

    const float* hb = hbuf + ((size_t)br * BATCH + b) * TT * HH;
    for (int idx = tid; idx < TT * HH; idx += 128)
        ((float*)os)[idx] = hb[idx];

    float vr[4];
    #pragma unroll
    for (int j = 0; j < 4; j++) vr[j] = v[lane + 32 * j];
    __syncthreads();

    for (int t = warp; t < TT; t += 4) {
        float p = 0.f;
        #pragma unroll
        for (int j = 0; j < 4; j++) p += os[t][lane + 32 * j] * vr[j];
        #pragma unroll
        for (int o = 16; o > 0; o >>= 1) p += __shfl_down_sync(0xffffffffu, p, o);
        if (lane == 0) sc[t] = p;
    }
    __syncthreads();

    if (warp == 0) {
        float x0 = (lane      < TT) ? sc[lane]      : -1e30f;
        float x1 = (lane + 32 < TT) ? sc[lane + 32] : -1e30f;
        float m = fmaxf(x0, x1);
        #pragma unroll
        for (int o = 16; o > 0; o >>= 1) m = fmaxf(m, __shfl_xor_sync(0xffffffffu, m, o));
        float e0 = (lane      < TT) ? expf(x0 - m) : 0.f;
        float e1 = (lane + 32 < TT) ? expf(x1 - m) : 0.f;
        float s = e0 + e1;
        #pragma unroll
        for (int o = 16; o > 0; o >>= 1) s += __shfl_xor_sync(0xffffffffu, s, o);
        float invs = 1.f / s;
        if (lane < TT)      sc[lane]      = e0 * invs;
        if (lane + 32 < TT) sc[lane + 32] = e1 * invs;
    }
    __syncthreads();

    float c = 0.f;
    for (int t = 0; t < TT; t++) c += sc[t] * os[t][tid];
    ctxs[tid] = c;
    __syncthreads();

    #pragma unroll
    for (int j = 0; j < 4; j++) {
        int n = tid + 128 * j;
        float acc = bo[n];
        #pragma unroll 4
        for (int h = 0; h < HH; h++) acc += ctxs[h] * __ldg(&Wo[h * 512 + n]);
        aout[(size_t)b * 1024 + br * 512 + n] = fmaxf(acc, 0.f);
    }
}

// ---------------------------------------------------------------------------
// Final logits
// ---------------------------------------------------------------------------
__global__ void __launch_bounds__(256) head_kernel(
    const float* __restrict__ hidden, const float* __restrict__ Wout,
    const float* __restrict__ bout, float* __restrict__ out)
{
    int tid = threadIdx.x;
    int b = tid >> 1, j = tid & 1;
    float acc = bout[j];
    #pragma unroll 4
    for (int k = 0; k < 512; k++) acc += hidden[b * 512 + k] * Wout[k * 2 + j];
    out[b * 2 + j] = acc;
}

// ---------------------------------------------------------------------------
extern "C" void kernel_launch(void* const* d_in, const int* in_sizes, int n_in,
                              void* d_out, int out_size)
{
    const float* x1    = (const float*)d_in[0];
    const float* x2    = (const float*)d_in[1];
    const float* emb1  = (const float*)d_in[2];
    const float* emb2  = (const float*)d_in[3];
    const float* Wl1   = (const float*)d_in[4];
    const float* Wl2   = (const float*)d_in[5];
    const float* lng1  = (const float*)d_in[6];
    const float* lnb1  = (const float*)d_in[7];
    const float* lng2  = (const float*)d_in[8];
    const float* lnb2  = (const float*)d_in[9];
    const float* av1   = (const float*)d_in[10];
    const float* aWo1  = (const float*)d_in[11];
    const float* abo1  = (const float*)d_in[12];
    const float* av2   = (const float*)d_in[13];
    const float* aWo2  = (const float*)d_in[14];
    const float* abo2  = (const float*)d_in[15];
    const float* Wh    = (const float*)d_in[16];
    const float* bh    = (const float*)d_in[17];
    const float* Wout  = (const float*)d_in[18];
    const float* bout  = (const float*)d_in[19];
    float* out = (float*)d_out;

    __nv_bfloat16 *pxhi, *pxlo, *pehiT, *peloT;
    float *pe, *pzx, *ph, *pa, *phid;
    cudaGetSymbolAddress((void**)&pxhi,  g_xhi);
    cudaGetSymbolAddress((void**)&pxlo,  g_xlo);
    cudaGetSymbolAddress((void**)&pehiT, g_ehiT);
    cudaGetSymbolAddress((void**)&peloT, g_eloT);
    cudaGetSymbolAddress((void**)&pe,    g_e);
    cudaGetSymbolAddress((void**)&pzx,   g_zx);
    cudaGetSymbolAddress((void**)&ph,    g_h);
    cudaGetSymbolAddress((void**)&pa,    g_a);
    cudaGetSymbolAddress((void**)&phid,  g_hidden);

    const int lstm_smem = (WSR * 512 + 128 * 4 + 4 * 128 + 4 * 4 * 128 + 16 * 4 * 2 + 4 * 4 * 2) * 4;
    cudaFuncSetAttribute(lstm_kernel, cudaFuncAttributeMaxDynamicSharedMemorySize, lstm_smem);

    // 0) convert x and embed to bf16 hi/lo (padded; embed transposed)
    {
        size_t nquad = (2L * MROWS * KSEG) / 4;
        int blocks = (int)((nquad + 255) / 256);
        convx_kernel<<<blocks, 256>>>(x1, x2, pxhi, pxlo);
    }
    {
        size_t tot = 2L * NPAD * KSEG;
        int blocks = (int)((tot + 255) / 256);
        conve_kernel<<<blocks, 256>>>(emb1, emb2, pehiT, peloT);
    }

    // 1) embeddings via bf16 split MMA: e = x @ embed
    emb_mma_kernel<<<dim3(NPAD / GBN, MROWS / GBM, 2), 256>>>(pxhi, pxlo, pehiT, peloT, pe);

    // 2) zx = e @ W_lstm[0:300]   [5888 x 512], K=300
    sgemm_kernel<<<dim3(4, 46), 256>>>(pe, Wl1, nullptr, pzx,
                                       MROWS, ZC, EE, EE, ZC, ZC, 0);
    sgemm_kernel<<<dim3(4, 46), 256>>>(pe + (size_t)MROWS * EE, Wl2, nullptr,
                                       pzx + (size_t)MROWS * ZC,
                                       MROWS, ZC, EE, EE, ZC, ZC, 0);

    // 3) recurrent LSTM, both branches
    lstm_kernel<<<64, 512, lstm_smem>>>(pzx, Wl1, Wl2, lng1, lnb1, lng2, lnb2, ph);

    // 4) attention + dense(512,relu)
    attn_kernel<<<dim3(BATCH, 2), 128>>>(ph, av1, aWo1, abo1, av2, aWo2, abo2, pa);

    // 5) hidden = relu(concat @ W_h + b_h)
    sgemm_kernel<<<dim3(4, 1), 256>>>(pa, Wh, bh, phid,
                                      BATCH, 512, 1024, 1024, 512, 512, 1);

    // 6) logits
    head_kernel<<<1, 256>>>(phid, Wout, bout, out);
}